// round 2
// baseline (speedup 1.0000x reference)
#include <cuda_runtime.h>
#include <math.h>

#define D 512
#define H 512
#define K_TOP 64
#define O 5
#define MAX_T 262144
#define HIST_BINS 65536
#define CAPB 16384
#define CAPB_SH 2048

// ---------------- device scratch (no allocation allowed) ----------------
__device__ float g_alpha[MAX_T];
__device__ unsigned int g_hist[HIST_BINS];
__device__ int g_thresh_bin;
__device__ int g_count_above;
__device__ int g_needed;
__device__ int g_cntA;
__device__ int g_cntB;
__device__ float g_valsA[K_TOP];
__device__ int   g_idxA[K_TOP];
__device__ float g_valsB[CAPB];
__device__ int   g_idxB[CAPB];
__device__ float g_gates[3 * H * 2];   // gi[0..1536), gh[1536..3072)

// monotonic float->uint key
__device__ __forceinline__ unsigned int fkey(float x) {
    unsigned int u = __float_as_uint(x);
    return (u & 0x80000000u) ? ~u : (u | 0x80000000u);
}

// ---------------- K0: zero scratch ----------------
__global__ void zero_kernel() {
    int i = blockIdx.x * blockDim.x + threadIdx.x;
    if (i < HIST_BINS) g_hist[i] = 0u;
    if (i == 0) { g_cntA = 0; g_cntB = 0; }
}

// ---------------- K1: alpha = fs @ fea, + histogram ----------------
// warp-per-row, float4 coalesced
__global__ void alpha_kernel(const float* __restrict__ fs,
                             const float* __restrict__ fea,
                             int T) {
    __shared__ float4 sfea[D / 4];
    int tid = threadIdx.x;
    if (tid < D / 4) sfea[tid] = reinterpret_cast<const float4*>(fea)[tid];
    __syncthreads();

    int warp = tid >> 5;
    int lane = tid & 31;
    int row = blockIdx.x * 8 + warp;     // 8 warps per block (256 threads)
    if (row >= T) return;

    const float4* rp = reinterpret_cast<const float4*>(fs + (size_t)row * D);
    float s = 0.f;
#pragma unroll
    for (int j = 0; j < 4; j++) {
        float4 a = rp[lane + 32 * j];
        float4 b = sfea[lane + 32 * j];
        s += a.x * b.x + a.y * b.y + a.z * b.z + a.w * b.w;
    }
#pragma unroll
    for (int off = 16; off > 0; off >>= 1)
        s += __shfl_down_sync(0xFFFFFFFFu, s, off);
    if (lane == 0) {
        g_alpha[row] = s;
        atomicAdd(&g_hist[fkey(s) >> 16], 1u);
    }
}

// ---------------- K2: suffix-scan histogram to find top-64 threshold ----
__global__ void thresh_kernel(int T) {
    __shared__ unsigned int chunk[1024];
    int tid = threadIdx.x;          // 1024 threads
    unsigned int s = 0;
    int base = tid * 64;
#pragma unroll 4
    for (int b = 0; b < 64; b++) s += g_hist[base + b];
    chunk[tid] = s;
    __syncthreads();
    if (tid == 0) {
        unsigned int above = 0;
        for (int c = 1023; c >= 0; --c) {
            if (above + chunk[c] >= K_TOP) {
                for (int b = c * 64 + 63; b >= c * 64; --b) {
                    unsigned int hc = g_hist[b];
                    if (above + hc >= K_TOP) {
                        g_thresh_bin = b;
                        g_count_above = (int)above;
                        g_needed = K_TOP - (int)above;
                        return;
                    }
                    above += hc;
                }
            }
            above += chunk[c];
        }
        // fallback (shouldn't happen, T >= 64)
        g_thresh_bin = 0; g_count_above = 0; g_needed = K_TOP;
    }
}

// ---------------- K3: compact candidates ----------------
__global__ void compact_kernel(int T) {
    int i = blockIdx.x * blockDim.x + threadIdx.x;
    if (i >= T) return;
    float v = g_alpha[i];
    int bin = (int)(fkey(v) >> 16);
    int tb = g_thresh_bin;
    if (bin > tb) {
        int p = atomicAdd(&g_cntA, 1);
        if (p < K_TOP) { g_valsA[p] = v; g_idxA[p] = i; }
    } else if (bin == tb) {
        int p = atomicAdd(&g_cntB, 1);
        if (p < CAPB) { g_valsB[p] = v; g_idxB[p] = i; }
    }
}

// ---------------- K_gru: gate GEMVs (warp per row) ----------------
__global__ void gru_gates_kernel(const float* __restrict__ w_ih,
                                 const float* __restrict__ w_hh,
                                 const float* __restrict__ fea,
                                 const float* __restrict__ h) {
    int warp = (blockIdx.x * blockDim.x + threadIdx.x) >> 5;
    int lane = threadIdx.x & 31;
    if (warp >= 3 * H * 2) return;
    const float* W;
    const float* v;
    if (warp < 3 * H) { W = w_ih + (size_t)warp * D; v = fea; }
    else              { W = w_hh + (size_t)(warp - 3 * H) * H; v = h; }
    const float4* wp = reinterpret_cast<const float4*>(W);
    const float4* vp = reinterpret_cast<const float4*>(v);
    float s = 0.f;
#pragma unroll
    for (int j = 0; j < 4; j++) {
        float4 a = wp[lane + 32 * j];
        float4 b = vp[lane + 32 * j];
        s += a.x * b.x + a.y * b.y + a.z * b.z + a.w * b.w;
    }
#pragma unroll
    for (int off = 16; off > 0; off >>= 1)
        s += __shfl_down_sync(0xFFFFFFFFu, s, off);
    if (lane == 0) g_gates[warp] = s;
}

// ---------------- K4: final (selection, softmax, attn, head, GRU) -------
__global__ void finalize_kernel(const float* __restrict__ fea,
                                const float* __restrict__ h,
                                const float* __restrict__ hs,
                                const float* __restrict__ b_ih,
                                const float* __restrict__ b_hh,
                                const float* __restrict__ W_out,
                                const float* __restrict__ b_out,
                                float* __restrict__ out) {
    __shared__ float topv[K_TOP];
    __shared__ int   topi[K_TOP];
    __shared__ float cv[CAPB_SH];
    __shared__ int   ci[CAPB_SH];
    __shared__ float attn[H];
    __shared__ float red[512];
    __shared__ int   ridx[512];
    __shared__ float wts[K_TOP];
    __shared__ float logits[O];

    int tid = threadIdx.x;   // 512 threads
    int cntA = min(g_cntA, K_TOP);
    int needed = K_TOP - cntA;
    for (int i = tid; i < cntA; i += 512) { topv[i] = g_valsA[i]; topi[i] = g_idxA[i]; }
    int m = min(g_cntB, CAPB_SH);
    for (int i = tid; i < m; i += 512) { cv[i] = g_valsB[i]; ci[i] = g_idxB[i]; }
    __syncthreads();

    // iterative argmax selection of `needed` boundary-bin elements
    for (int s = 0; s < needed; s++) {
        float best = -INFINITY; int bj = -1;
        for (int i = tid; i < m; i += 512)
            if (cv[i] > best) { best = cv[i]; bj = i; }
        red[tid] = best; ridx[tid] = bj;
        __syncthreads();
        for (int off = 256; off > 0; off >>= 1) {
            if (tid < off && red[tid + off] > red[tid]) {
                red[tid] = red[tid + off]; ridx[tid] = ridx[tid + off];
            }
            __syncthreads();
        }
        if (tid == 0) {
            int j = ridx[0];
            topv[cntA + s] = cv[j];
            topi[cntA + s] = ci[j];
            cv[j] = -INFINITY;
        }
        __syncthreads();
    }

    // softmax over the 64 selected scores
    if (tid == 0) {
        float mx = -INFINITY;
        for (int k = 0; k < K_TOP; k++) mx = fmaxf(mx, topv[k]);
        float ssum = 0.f;
        for (int k = 0; k < K_TOP; k++) { float e = expf(topv[k] - mx); wts[k] = e; ssum += e; }
        float inv = 1.f / ssum;
        for (int k = 0; k < K_TOP; k++) wts[k] *= inv;
    }
    __syncthreads();

    // attn_h = w @ hs[idx]
    {
        float a = 0.f;
#pragma unroll 4
        for (int k = 0; k < K_TOP; k++)
            a += wts[k] * hs[(size_t)topi[k] * H + tid];
        attn[tid] = a;
    }
    __syncthreads();

    // prediction head: logits = W_out @ [fea, attn, h, 64] + b_out
    float fv = fea[tid];
    float hv = h[tid];
    for (int o = 0; o < O; o++) {
        const float* Wr = W_out + (size_t)o * (D + 2 * H + 1);
        float p = Wr[tid] * fv + Wr[D + tid] * attn[tid] + Wr[D + H + tid] * hv;
        red[tid] = p;
        __syncthreads();
        for (int off = 256; off > 0; off >>= 1) {
            if (tid < off) red[tid] += red[tid + off];
            __syncthreads();
        }
        if (tid == 0) logits[o] = red[0] + Wr[D + 2 * H] * (float)K_TOP + b_out[o];
        __syncthreads();
    }
    if (tid == 0) {
        float mx = logits[0];
        for (int o = 1; o < O; o++) mx = fmaxf(mx, logits[o]);
        float ssum = 0.f;
        for (int o = 0; o < O; o++) ssum += expf(logits[o] - mx);
        float lse = mx + logf(ssum);
        for (int o = 0; o < O; o++) out[o] = logits[o] - lse;
    }

    // GRU finalize: h_new
    {
        float gi_r = g_gates[tid]            + b_ih[tid];
        float gh_r = g_gates[3 * H + tid]    + b_hh[tid];
        float gi_z = g_gates[H + tid]        + b_ih[H + tid];
        float gh_z = g_gates[3 * H + H + tid]+ b_hh[H + tid];
        float gi_n = g_gates[2 * H + tid]        + b_ih[2 * H + tid];
        float gh_n = g_gates[3 * H + 2 * H + tid]+ b_hh[2 * H + tid];
        float r = 1.f / (1.f + expf(-(gi_r + gh_r)));
        float z = 1.f / (1.f + expf(-(gi_z + gh_z)));
        float n = tanhf(gi_n + r * gh_n);
        out[O + tid] = (1.f - z) * n + z * hv;
    }
}

// ---------------- launcher ----------------
extern "C" void kernel_launch(void* const* d_in, const int* in_sizes, int n_in,
                              void* d_out, int out_size) {
    const float* fea   = (const float*)d_in[0];
    const float* h     = (const float*)d_in[1];
    const float* fs    = (const float*)d_in[2];
    const float* hs    = (const float*)d_in[3];
    const float* w_ih  = (const float*)d_in[4];
    const float* w_hh  = (const float*)d_in[5];
    const float* b_ih  = (const float*)d_in[6];
    const float* b_hh  = (const float*)d_in[7];
    const float* W_out = (const float*)d_in[8];
    const float* b_out = (const float*)d_in[9];
    float* out = (float*)d_out;

    int T = in_sizes[2] / D;
    if (T > MAX_T) T = MAX_T;

    zero_kernel<<<(HIST_BINS + 255) / 256, 256>>>();
    alpha_kernel<<<(T + 7) / 8, 256>>>(fs, fea, T);
    thresh_kernel<<<1, 1024>>>(T);
    compact_kernel<<<(T + 255) / 256, 256>>>(T);
    gru_gates_kernel<<<(3 * H * 2 * 32 + 255) / 256, 256>>>(w_ih, w_hh, fea, h);
    finalize_kernel<<<1, 512>>>(fea, h, hs, b_ih, b_hh, W_out, b_out, out);
}

// round 3
// speedup vs baseline: 1.3509x; 1.3509x over previous
#include <cuda_runtime.h>
#include <math.h>

#define D 512
#define H 512
#define K_TOP 64
#define O 5
#define MAX_T 262144
#define HIST_BINS 65536
#define CAPB 16384
#define CAPB_SH 2048

// ---------------- device scratch (no allocation allowed) ----------------
__device__ float g_alpha[MAX_T];
__device__ unsigned int g_hist[HIST_BINS];
__device__ int g_thresh_bin;
__device__ int g_count_above;
__device__ int g_cntA;
__device__ int g_cntB;
__device__ float g_valsA[K_TOP];
__device__ int   g_idxA[K_TOP];
__device__ float g_valsB[CAPB];
__device__ int   g_idxB[CAPB];
__device__ float g_gates[3 * H * 2];   // gi[0..1536), gh[1536..3072)

// monotonic float->uint key
__device__ __forceinline__ unsigned int fkey(float x) {
    unsigned int u = __float_as_uint(x);
    return (u & 0x80000000u) ? ~u : (u | 0x80000000u);
}

// ---------------- K0: prelude — zero hist + GRU gate GEMVs (independent of alpha)
__global__ void prelude_kernel(const float* __restrict__ w_ih,
                               const float* __restrict__ w_hh,
                               const float* __restrict__ fea,
                               const float* __restrict__ h) {
    int gid = blockIdx.x * blockDim.x + threadIdx.x;   // 384 blocks * 256 = 98304
    if (gid < HIST_BINS) g_hist[gid] = 0u;
    if (gid == 0) { g_cntA = 0; g_cntB = 0; }

    int warp = gid >> 5;        // 3072 warps total
    int lane = threadIdx.x & 31;
    if (warp >= 3 * H * 2) return;
    const float* W;
    const float* v;
    if (warp < 3 * H) { W = w_ih + (size_t)warp * D; v = fea; }
    else              { W = w_hh + (size_t)(warp - 3 * H) * H; v = h; }
    const float4* wp = reinterpret_cast<const float4*>(W);
    const float4* vp = reinterpret_cast<const float4*>(v);
    float s = 0.f;
#pragma unroll
    for (int j = 0; j < 4; j++) {
        float4 a = wp[lane + 32 * j];
        float4 b = vp[lane + 32 * j];
        s += a.x * b.x + a.y * b.y + a.z * b.z + a.w * b.w;
    }
#pragma unroll
    for (int off = 16; off > 0; off >>= 1)
        s += __shfl_down_sync(0xFFFFFFFFu, s, off);
    if (lane == 0) g_gates[warp] = s;
}

// ---------------- K1: alpha = fs @ fea, + histogram ----------------
__global__ void alpha_kernel(const float* __restrict__ fs,
                             const float* __restrict__ fea,
                             int T) {
    __shared__ float4 sfea[D / 4];
    int tid = threadIdx.x;
    if (tid < D / 4) sfea[tid] = reinterpret_cast<const float4*>(fea)[tid];
    __syncthreads();

    int warp = tid >> 5;
    int lane = tid & 31;
    int row = blockIdx.x * 8 + warp;     // 8 warps per block (256 threads)
    if (row >= T) return;

    const float4* rp = reinterpret_cast<const float4*>(fs + (size_t)row * D);
    float s = 0.f;
#pragma unroll
    for (int j = 0; j < 4; j++) {
        float4 a = rp[lane + 32 * j];
        float4 b = sfea[lane + 32 * j];
        s += a.x * b.x + a.y * b.y + a.z * b.z + a.w * b.w;
    }
#pragma unroll
    for (int off = 16; off > 0; off >>= 1)
        s += __shfl_down_sync(0xFFFFFFFFu, s, off);
    if (lane == 0) {
        g_alpha[row] = s;
        atomicAdd(&g_hist[fkey(s) >> 16], 1u);
    }
}

// ---------------- K2: parallel suffix-scan threshold finder ----------------
__global__ void thresh_kernel() {
    __shared__ unsigned int csum[1024];
    __shared__ unsigned int sbins[64];
    __shared__ int s_cstar;
    __shared__ unsigned int s_above;
    int t = threadIdx.x;  // 1024 threads

    // chunk sums: chunk t = bins [t*64, t*64+64)
    const uint4* hp = reinterpret_cast<const uint4*>(g_hist);
    unsigned int s = 0;
#pragma unroll
    for (int j = 0; j < 16; j++) {
        uint4 v = hp[t * 16 + j];
        s += v.x + v.y + v.z + v.w;
    }
    csum[t] = s;
    __syncthreads();

    // Hillis-Steele inclusive suffix scan
    for (int off = 1; off < 1024; off <<= 1) {
        unsigned int add = (t + off < 1024) ? csum[t + off] : 0u;
        __syncthreads();
        csum[t] += add;
        __syncthreads();
    }

    // c* = max c with suffix(c) >= K
    bool hit = (csum[t] >= K_TOP) && (t == 1023 || csum[t + 1] < K_TOP);
    if (hit) {
        s_cstar = t;
        s_above = (t < 1023) ? csum[t + 1] : 0u;
    }
    __syncthreads();
    int cstar = s_cstar;
    if (t < 64) sbins[t] = g_hist[cstar * 64 + t];
    __syncthreads();

    if (t == 0) {
        unsigned int above = s_above;
        int tb = cstar * 64;
        for (int b = 63; b >= 0; --b) {
            unsigned int hc = sbins[b];
            if (above + hc >= K_TOP) { tb = cstar * 64 + b; break; }
            above += hc;
        }
        g_thresh_bin = tb;
        g_count_above = (int)above;
    }
}

// ---------------- K3: compact candidates (float4) ----------------
__device__ __forceinline__ void push_cand(float v, int idx, int tb) {
    int bin = (int)(fkey(v) >> 16);
    if (bin > tb) {
        int p = atomicAdd(&g_cntA, 1);
        if (p < K_TOP) { g_valsA[p] = v; g_idxA[p] = idx; }
    } else if (bin == tb) {
        int p = atomicAdd(&g_cntB, 1);
        if (p < CAPB) { g_valsB[p] = v; g_idxB[p] = idx; }
    }
}

__global__ void compact_kernel(int T) {
    int i = blockIdx.x * blockDim.x + threadIdx.x;   // one float4 per thread
    int base = i * 4;
    if (base + 3 < T) {
        float4 v = reinterpret_cast<const float4*>(g_alpha)[i];
        int tb = g_thresh_bin;
        push_cand(v.x, base + 0, tb);
        push_cand(v.y, base + 1, tb);
        push_cand(v.z, base + 2, tb);
        push_cand(v.w, base + 3, tb);
    } else if (base < T) {
        int tb = g_thresh_bin;
        for (int j = base; j < T; j++) push_cand(g_alpha[j], j, tb);
    }
}

// ---------------- K4: final (selection, softmax, attn, head, GRU) -------
__global__ void finalize_kernel(const float* __restrict__ fea,
                                const float* __restrict__ h,
                                const float* __restrict__ hs,
                                const float* __restrict__ b_ih,
                                const float* __restrict__ b_hh,
                                const float* __restrict__ W_out,
                                const float* __restrict__ b_out,
                                float* __restrict__ out) {
    __shared__ float topv[K_TOP];
    __shared__ int   topi[K_TOP];
    __shared__ float cv[CAPB_SH];
    __shared__ int   ci[CAPB_SH];
    __shared__ float attn[H];
    __shared__ float red[512];
    __shared__ int   ridx[512];
    __shared__ float wts[K_TOP];
    __shared__ float logits[O];

    int tid = threadIdx.x;   // 512 threads
    int cntA = min(g_cntA, K_TOP);
    int needed = K_TOP - cntA;
    for (int i = tid; i < cntA; i += 512) { topv[i] = g_valsA[i]; topi[i] = g_idxA[i]; }
    int m = min(g_cntB, CAPB_SH);
    for (int i = tid; i < m; i += 512) { cv[i] = g_valsB[i]; ci[i] = g_idxB[i]; }
    __syncthreads();

    // iterative argmax selection of `needed` boundary-bin elements
    for (int s = 0; s < needed; s++) {
        float best = -INFINITY; int bj = -1;
        for (int i = tid; i < m; i += 512)
            if (cv[i] > best) { best = cv[i]; bj = i; }
        red[tid] = best; ridx[tid] = bj;
        __syncthreads();
        for (int off = 256; off > 0; off >>= 1) {
            if (tid < off && red[tid + off] > red[tid]) {
                red[tid] = red[tid + off]; ridx[tid] = ridx[tid + off];
            }
            __syncthreads();
        }
        if (tid == 0) {
            int j = ridx[0];
            topv[cntA + s] = cv[j];
            topi[cntA + s] = ci[j];
            cv[j] = -INFINITY;
        }
        __syncthreads();
    }

    // softmax over the 64 selected scores
    if (tid == 0) {
        float mx = -INFINITY;
        for (int k = 0; k < K_TOP; k++) mx = fmaxf(mx, topv[k]);
        float ssum = 0.f;
        for (int k = 0; k < K_TOP; k++) { float e = expf(topv[k] - mx); wts[k] = e; ssum += e; }
        float inv = 1.f / ssum;
        for (int k = 0; k < K_TOP; k++) wts[k] *= inv;
    }
    __syncthreads();

    // attn_h = w @ hs[idx]
    {
        float a = 0.f;
#pragma unroll 4
        for (int k = 0; k < K_TOP; k++)
            a += wts[k] * hs[(size_t)topi[k] * H + tid];
        attn[tid] = a;
    }
    __syncthreads();

    // prediction head: logits = W_out @ [fea, attn, h, 64] + b_out
    float fv = fea[tid];
    float hv = h[tid];
    for (int o = 0; o < O; o++) {
        const float* Wr = W_out + (size_t)o * (D + 2 * H + 1);
        float p = Wr[tid] * fv + Wr[D + tid] * attn[tid] + Wr[D + H + tid] * hv;
        red[tid] = p;
        __syncthreads();
        for (int off = 256; off > 0; off >>= 1) {
            if (tid < off) red[tid] += red[tid + off];
            __syncthreads();
        }
        if (tid == 0) logits[o] = red[0] + Wr[D + 2 * H] * (float)K_TOP + b_out[o];
        __syncthreads();
    }
    if (tid == 0) {
        float mx = logits[0];
        for (int o = 1; o < O; o++) mx = fmaxf(mx, logits[o]);
        float ssum = 0.f;
        for (int o = 0; o < O; o++) ssum += expf(logits[o] - mx);
        float lse = mx + logf(ssum);
        for (int o = 0; o < O; o++) out[o] = logits[o] - lse;
    }

    // GRU finalize: h_new
    {
        float gi_r = g_gates[tid]             + b_ih[tid];
        float gh_r = g_gates[3 * H + tid]     + b_hh[tid];
        float gi_z = g_gates[H + tid]         + b_ih[H + tid];
        float gh_z = g_gates[3 * H + H + tid] + b_hh[H + tid];
        float gi_n = g_gates[2 * H + tid]         + b_ih[2 * H + tid];
        float gh_n = g_gates[3 * H + 2 * H + tid] + b_hh[2 * H + tid];
        float r = 1.f / (1.f + expf(-(gi_r + gh_r)));
        float z = 1.f / (1.f + expf(-(gi_z + gh_z)));
        float n = tanhf(gi_n + r * gh_n);
        out[O + tid] = (1.f - z) * n + z * hv;
    }
}

// ---------------- launcher ----------------
extern "C" void kernel_launch(void* const* d_in, const int* in_sizes, int n_in,
                              void* d_out, int out_size) {
    const float* fea   = (const float*)d_in[0];
    const float* h     = (const float*)d_in[1];
    const float* fs    = (const float*)d_in[2];
    const float* hs    = (const float*)d_in[3];
    const float* w_ih  = (const float*)d_in[4];
    const float* w_hh  = (const float*)d_in[5];
    const float* b_ih  = (const float*)d_in[6];
    const float* b_hh  = (const float*)d_in[7];
    const float* W_out = (const float*)d_in[8];
    const float* b_out = (const float*)d_in[9];
    float* out = (float*)d_out;

    int T = in_sizes[2] / D;
    if (T > MAX_T) T = MAX_T;

    prelude_kernel<<<384, 256>>>(w_ih, w_hh, fea, h);        // zero hist + GRU gates
    alpha_kernel<<<(T + 7) / 8, 256>>>(fs, fea, T);
    thresh_kernel<<<1, 1024>>>();
    compact_kernel<<<(T / 4 + 255) / 256, 256>>>(T);
    finalize_kernel<<<1, 512>>>(fea, h, hs, b_ih, b_hh, W_out, b_out, out);
}